// round 16
// baseline (speedup 1.0000x reference)
#include <cuda_runtime.h>
#include <cuda_bf16.h>
#include <cstdint>
#include <math.h>

#define BATCH 32

// ================= scratch (device globals) =================
__device__ __align__(256) __nv_bfloat16 g_w1_hi[256*512],  g_w1_lo[256*512];
__device__ __align__(256) __nv_bfloat16 g_wv_hi[256*256],  g_wv_lo[256*256];
__device__ __align__(256) __nv_bfloat16 g_w2_hi[512*256],  g_w2_lo[512*256];
__device__ float g_bv[256];
__device__ float g_r[256];
__device__ __align__(256) __nv_bfloat16 g_M2_hi[256*256],  g_M2_lo[256*256];
__device__ __align__(256) __nv_bfloat16 g_G_hi[1024*256],  g_G_lo[1024*256];
__device__ float g_S[(size_t)BATCH*1024];
__device__ float g_Sp[(size_t)BATCH*1024*16];
__device__ __align__(256) __nv_bfloat16 g_xT_hi[(size_t)BATCH*1024*512], g_xT_lo[(size_t)BATCH*1024*512];
__device__ __align__(256) __nv_bfloat16 g_x1T_hi[(size_t)BATCH*1024*256], g_x1T_lo[(size_t)BATCH*1024*256];
__device__ __align__(256) __nv_bfloat16 g_uT_hi[(size_t)BATCH*1024*256], g_uT_lo[(size_t)BATCH*1024*256];
__device__ __align__(256) __nv_bfloat16 g_v_hi[(size_t)BATCH*256*1024],  g_v_lo[(size_t)BATCH*256*1024];
__device__ __align__(256) __nv_bfloat16 g_attn[(size_t)BATCH*1024*1024];
__device__ __align__(256) __nv_bfloat16 g_outT_hi[(size_t)BATCH*1024*256], g_outT_lo[(size_t)BATCH*1024*256];

// ================= helpers =================
__device__ __forceinline__ uint32_t smem_u32(const void* p) {
    uint32_t a;
    asm("{ .reg .u64 t; cvta.to.shared.u64 t, %1; cvt.u32.u64 %0, t; }" : "=r"(a) : "l"(p));
    return a;
}
__device__ __forceinline__ void cp16(uint32_t s, const void* g) {
    asm volatile("cp.async.cg.shared.global [%0], [%1], 16;" :: "r"(s), "l"(g) : "memory");
}
#define CP_COMMIT() asm volatile("cp.async.commit_group;" ::: "memory")
#define CP_WAIT0()  asm volatile("cp.async.wait_group 0;" ::: "memory")
#define CP_WAIT1()  asm volatile("cp.async.wait_group 1;" ::: "memory")

__device__ __forceinline__ void ldsm4(uint32_t* r, uint32_t addr) {
    asm volatile("ldmatrix.sync.aligned.m8n8.x4.shared.b16 {%0,%1,%2,%3}, [%4];"
        : "=r"(r[0]), "=r"(r[1]), "=r"(r[2]), "=r"(r[3]) : "r"(addr));
}
__device__ __forceinline__ void mma16816(float* c, const uint32_t* a, const uint32_t* b) {
    asm volatile("mma.sync.aligned.m16n8k16.row.col.f32.bf16.bf16.f32 "
        "{%0,%1,%2,%3}, {%4,%5,%6,%7}, {%8,%9}, {%0,%1,%2,%3};"
        : "+f"(c[0]), "+f"(c[1]), "+f"(c[2]), "+f"(c[3])
        : "r"(a[0]), "r"(a[1]), "r"(a[2]), "r"(a[3]), "r"(b[0]), "r"(b[1]));
}
__device__ __forceinline__ void bsplit(float v, __nv_bfloat16& h, __nv_bfloat16& l) {
    h = __float2bfloat16(v);
    l = __float2bfloat16(v - __bfloat162float(h));
}
__device__ __forceinline__ void split_pair(float v0, float v1, uint32_t& hi2, uint32_t& lo2) {
    __nv_bfloat16 h0, l0, h1, l1;
    bsplit(v0, h0, l0); bsplit(v1, h1, l1);
    __nv_bfloat162 h = __nv_bfloat162(h0, h1), l = __nv_bfloat162(l0, l1);
    hi2 = *reinterpret_cast<uint32_t*>(&h);
    lo2 = *reinterpret_cast<uint32_t*>(&l);
}

// MUFU-free exp: e^x via FMA/ALU only. Max rel err ~4e-5.
__device__ __forceinline__ float fast_exp(float x) {
    float y = x * 1.442695041f;                       // log2(e)
    y = fminf(fmaxf(y, -120.0f), 120.0f);
    float n = rintf(y);
    float f = y - n;                                  // [-0.5, 0.5]
    // e^(f*ln2), Taylor deg 4 about 0
    float p = fmaf(f, 0.009618129f, 0.055504109f);
    p = fmaf(f, p, 0.240226507f);
    p = fmaf(f, p, 0.693147181f);
    p = fmaf(f, p, 1.0f);
    int ni = __float2int_rn(n);
    float sc = __int_as_float((ni + 127) << 23);
    return p * sc;
}
__device__ __forceinline__ float silu(float t) { return t / (1.0f + fast_exp(-t)); }

// ================= prep kernels =================
__global__ void prep_w(const float* __restrict__ w1, const float* __restrict__ vw,
                       const float* __restrict__ vb, const float* __restrict__ w2) {
    int t = blockIdx.x * blockDim.x + threadIdx.x;
    if (t < 256*512) bsplit(w1[t], g_w1_hi[t], g_w1_lo[t]);
    if (t < 256*256) bsplit(vw[t], g_wv_hi[t], g_wv_lo[t]);
    if (t < 512*256) bsplit(w2[t], g_w2_hi[t], g_w2_lo[t]);
    if (t < 256) g_bv[t] = vb[t];
}

// M2[a][b] = sum_o Wq[o][a]*Wk[o][b]; block 256 computes r[b] = sum_o bq[o]*Wk[o][b]
__global__ void m2_kernel(const float* __restrict__ qw, const float* __restrict__ kw,
                          const float* __restrict__ qb) {
    int a = blockIdx.x, bcol = threadIdx.x;
    float acc = 0.f;
    if (a < 256) {
        for (int o = 0; o < 256; o++) acc += qw[o*256 + a] * kw[o*256 + bcol];
        bsplit(acc, g_M2_hi[a*256 + bcol], g_M2_lo[a*256 + bcol]);
    } else {
        for (int o = 0; o < 256; o++) acc += qb[o] * kw[o*256 + bcol];
        g_r[bcol] = acc;
    }
}

// G'[i][b] = sum_a pos[a][i]*We[a][b] + r[b]   (m2_kernel runs first)
__global__ void g_kernel(const float* __restrict__ ew, const float* __restrict__ rh,
                         const float* __restrict__ rw) {
    int i = blockIdx.x, bcol = threadIdx.x;
    int h = i >> 5, w = i & 31;
    float acc = g_r[bcol];
    for (int a = 0; a < 256; a++) {
        float pv = rh[a*32 + h] + rw[a*32 + w];
        acc += pv * ew[a*256 + bcol];
    }
    bsplit(acc, g_G_hi[i*256 + bcol], g_G_lo[i*256 + bcol]);
}

// S[row] = sum of 16 per-jblock partials
__global__ void sum16_k() {
    int t = blockIdx.x * blockDim.x + threadIdx.x;   // 32768
    const float* p = g_Sp + (size_t)t * 16;
    float s = 0.f;
#pragma unroll
    for (int c = 0; c < 16; c++) s += p[c];
    g_S[t] = s;
}

// transpose + split x: [b][d][n] fp32 -> xT[b][n][d] bf16 hi/lo
__global__ void xt_conv(const float* __restrict__ x) {
    __shared__ float tile[32][33];
    int b = blockIdx.z, d0 = blockIdx.y*32, n0 = blockIdx.x*32;
    int tx = threadIdx.x, ty = threadIdx.y;  // 32 x 8
    const float* xp = x + ((size_t)b*512 + d0)*1024 + n0;
#pragma unroll
    for (int r = 0; r < 4; r++) tile[ty + r*8][tx] = xp[(size_t)(ty + r*8)*1024 + tx];
    __syncthreads();
#pragma unroll
    for (int r = 0; r < 4; r++) {
        int nl = ty + r*8;
        __nv_bfloat16 h, l; bsplit(tile[tx][nl], h, l);
        size_t o = ((size_t)b*1024 + n0 + nl)*512 + d0 + tx;
        g_xT_hi[o] = h; g_xT_lo[o] = l;
    }
}

// ===== fused-3-product warp-MMA GEMM, occupancy-3 geometry (R15-proven) =====
// CTA 128x64, BK=32, 8 warps (4x2) of 32x32, 3-stage pipeline, 3 CTAs/SM.
// MODE 0: cv1    M=n(1024) N=c(256)  K=512  -> x1T
// MODE 1: u      M=n(1024) N=a(256)  K=256  -> uT
// MODE 2: v      M=c(256)  N=n(1024) K=256  -> v
// MODE 3: logits M=i(1024) N=j(1024) K=512  -> E bf16 + row partials (16 jblocks)
// MODE 4: out    M=i(1024) N=c(256)  K=1024 -> outT
// MODE 5: cv2    M=d(512)  N=n(1024) K=256  -> d_out
#define A_TILE 8192
#define B_TILE 4096
#define STAGE_BYTES 24576
#define SMEM_BYTES  73728

template <int MODE>
__global__ void __launch_bounds__(256, 3)
gemm_mma(const float* __restrict__ p0, const float* __restrict__ p1,
         const float* __restrict__ p2, float* __restrict__ pout) {
    constexpr int K   = (MODE==0 || MODE==3) ? 512 : (MODE==4 ? 1024 : 256);
    constexpr int KIT = K / 32;
    constexpr int ST  = (MODE==0) ? 512 : (MODE==4 ? 1024 : 256);
    constexpr bool ALO = (MODE != 4);

    extern __shared__ char smem[];
    const uint32_t sbase = smem_u32(smem);
    const int tid = threadIdx.x, wid = tid >> 5, lane = tid & 31;
    const int b = blockIdx.z, m0 = blockIdx.y * 128, n0 = blockIdx.x * 64;
    const int warpM = (wid & 3) * 32, warpN = (wid >> 2) * 32;
    const int rsel = lane & 15, csel = lane >> 4;

    uint32_t aSw[2]; int aRow[2], aQ[2];
#pragma unroll
    for (int c = 0; c < 2; c++) {
        int idx = tid + c*256;
        aRow[c] = idx >> 2; aQ[c] = idx & 3;
        aSw[c] = (uint32_t)(aRow[c]*64 + ((aQ[c] ^ ((aRow[c] >> 1) & 3)) << 4));
    }
    const int bRow = tid >> 2, bQ = tid & 3;
    const uint32_t bSw = (uint32_t)(bRow*64 + ((bQ ^ ((bRow >> 1) & 3)) << 4));

    uint32_t offA[2][2], offB[2][2];
#pragma unroll
    for (int fi = 0; fi < 2; fi++) {
        int row = warpM + fi*16 + rsel;
        int rsw = (row >> 1) & 3;
#pragma unroll
        for (int ks = 0; ks < 2; ks++)
            offA[fi][ks] = (uint32_t)(row*64 + (((ks*2 + csel) ^ rsw) << 4));
    }
#pragma unroll
    for (int fj = 0; fj < 2; fj++) {
        int row = warpN + fj*16 + rsel;
        int rsw = (row >> 1) & 3;
#pragma unroll
        for (int ks = 0; ks < 2; ks++)
            offB[fj][ks] = (uint32_t)(row*64 + (((ks*2 + csel) ^ rsw) << 4));
    }

    const __nv_bfloat16 *pAh, *pAl, *pBh, *pBl;
    auto get_ptrs = [&](int kc) {
        if (MODE == 0) {
            size_t ao = ((size_t)b*1024 + m0)*512 + kc*32;
            pAh = g_xT_hi + ao; pAl = g_xT_lo + ao;
            size_t bo = (size_t)n0*512 + kc*32;
            pBh = g_w1_hi + bo; pBl = g_w1_lo + bo;
        } else if (MODE == 1) {
            size_t ao = ((size_t)b*1024 + m0)*256 + kc*32;
            pAh = g_x1T_hi + ao; pAl = g_x1T_lo + ao;
            size_t bo = (size_t)n0*256 + kc*32;
            pBh = g_M2_hi + bo; pBl = g_M2_lo + bo;
        } else if (MODE == 2) {
            size_t ao = (size_t)m0*256 + kc*32;
            pAh = g_wv_hi + ao; pAl = g_wv_lo + ao;
            size_t bo = ((size_t)b*1024 + n0)*256 + kc*32;
            pBh = g_x1T_hi + bo; pBl = g_x1T_lo + bo;
        } else if (MODE == 3) {
            if (kc < 8) {
                size_t ao = ((size_t)b*1024 + m0)*256 + kc*32;
                pAh = g_x1T_hi + ao; pAl = g_x1T_lo + ao;
                size_t bo = ((size_t)b*1024 + n0)*256 + kc*32;
                pBh = g_uT_hi + bo; pBl = g_uT_lo + bo;
            } else {
                size_t ao = (size_t)m0*256 + (kc - 8)*32;
                pAh = g_G_hi + ao; pAl = g_G_lo + ao;
                size_t bo = ((size_t)b*1024 + n0)*256 + (kc - 8)*32;
                pBh = g_x1T_hi + bo; pBl = g_x1T_lo + bo;
            }
        } else if (MODE == 4) {
            size_t ao = ((size_t)b*1024 + m0)*1024 + kc*32;
            pAh = g_attn + ao; pAl = pAh;
            size_t bo = ((size_t)b*256 + n0)*1024 + kc*32;
            pBh = g_v_hi + bo; pBl = g_v_lo + bo;
        } else {
            size_t ao = (size_t)m0*256 + kc*32;
            pAh = g_w2_hi + ao; pAl = g_w2_lo + ao;
            size_t bo = ((size_t)b*1024 + n0)*256 + kc*32;
            pBh = g_outT_hi + bo; pBl = g_outT_lo + bo;
        }
    };
    auto issue = [&](int buf) {
        uint32_t s0 = sbase + (uint32_t)buf*STAGE_BYTES;
#pragma unroll
        for (int c = 0; c < 2; c++) {
            size_t go = (size_t)aRow[c]*ST + aQ[c]*8;
            cp16(s0 + aSw[c], pAh + go);
            if (ALO) cp16(s0 + A_TILE + aSw[c], pAl + go);
        }
        size_t gb = (size_t)bRow*ST + bQ*8;
        cp16(s0 + 2*A_TILE + bSw, pBh + gb);
        cp16(s0 + 2*A_TILE + B_TILE + bSw, pBl + gb);
        CP_COMMIT();
    };

    float acc[2][4][4] = {};

    get_ptrs(0); issue(0);
    get_ptrs(1); issue(1);
    CP_WAIT1();
    __syncthreads();

    int buf = 0;
    for (int it = 0; it < KIT; ++it) {
        if (it + 2 < KIT) {
            get_ptrs(it + 2);
            issue((buf + 2) % 3);
        }
        const uint32_t aH = sbase + (uint32_t)buf*STAGE_BYTES;
        const uint32_t aL = aH + A_TILE;
        const uint32_t bH = aH + 2*A_TILE;
        const uint32_t bL = bH + B_TILE;
#pragma unroll
        for (int ks = 0; ks < 2; ++ks) {
            uint32_t ah[2][4], bh[2][4], bl[2][4];
#pragma unroll
            for (int fi = 0; fi < 2; fi++) ldsm4(ah[fi], aH + offA[fi][ks]);
#pragma unroll
            for (int fj = 0; fj < 2; fj++) ldsm4(bh[fj], bH + offB[fj][ks]);
#pragma unroll
            for (int fj = 0; fj < 2; fj++) ldsm4(bl[fj], bL + offB[fj][ks]);
#pragma unroll
            for (int fi = 0; fi < 2; fi++)
#pragma unroll
                for (int fj = 0; fj < 4; fj++) {
                    uint32_t bb[2] = { bh[fj >> 1][fj & 1], bh[fj >> 1][2 + (fj & 1)] };
                    mma16816(acc[fi][fj], ah[fi], bb);
                }
#pragma unroll
            for (int fi = 0; fi < 2; fi++)
#pragma unroll
                for (int fj = 0; fj < 4; fj++) {
                    uint32_t bb[2] = { bl[fj >> 1][fj & 1], bl[fj >> 1][2 + (fj & 1)] };
                    mma16816(acc[fi][fj], ah[fi], bb);
                }
            if (ALO) {
                uint32_t al[2][4];
#pragma unroll
                for (int fi = 0; fi < 2; fi++) ldsm4(al[fi], aL + offA[fi][ks]);
#pragma unroll
                for (int fi = 0; fi < 2; fi++)
#pragma unroll
                    for (int fj = 0; fj < 4; fj++) {
                        uint32_t bb[2] = { bh[fj >> 1][fj & 1], bh[fj >> 1][2 + (fj & 1)] };
                        mma16816(acc[fi][fj], al[fi], bb);
                    }
            }
        }
        if (it + 1 < KIT) {
            if (it + 2 < KIT) CP_WAIT1(); else CP_WAIT0();
            __syncthreads();
        }
        buf = (buf + 1) % 3;
    }

    // ---- epilogue ----
    const float rs = rsqrtf(1.0f + 1e-5f);
    float rsum[2][2] = {};
#pragma unroll
    for (int fi = 0; fi < 2; fi++) {
        int r0 = m0 + warpM + fi*16 + (lane >> 2);
#pragma unroll
        for (int fj = 0; fj < 4; fj++) {
            int c = n0 + warpN + fj*8 + (lane & 3)*2;
#pragma unroll
            for (int h = 0; h < 2; h++) {
                int r = r0 + h*8;
                float v0 = acc[fi][fj][h*2], v1 = acc[fi][fj][h*2 + 1];
                if (MODE == 0) {
                    float t0 = fmaf(v0, p0[c]*rs,   p1[c]);
                    float t1 = fmaf(v1, p0[c+1]*rs, p1[c+1]);
                    uint32_t hi2, lo2; split_pair(silu(t0), silu(t1), hi2, lo2);
                    size_t o = ((size_t)b*1024 + r)*256 + c;
                    *reinterpret_cast<uint32_t*>(&g_x1T_hi[o]) = hi2;
                    *reinterpret_cast<uint32_t*>(&g_x1T_lo[o]) = lo2;
                } else if (MODE == 1) {
                    uint32_t hi2, lo2; split_pair(v0, v1, hi2, lo2);
                    size_t o = ((size_t)b*1024 + r)*256 + c;
                    *reinterpret_cast<uint32_t*>(&g_uT_hi[o]) = hi2;
                    *reinterpret_cast<uint32_t*>(&g_uT_lo[o]) = lo2;
                } else if (MODE == 2) {
                    float bi = g_bv[r];
                    uint32_t hi2, lo2; split_pair(v0 + bi, v1 + bi, hi2, lo2);
                    size_t o = ((size_t)b*256 + r)*1024 + c;
                    *reinterpret_cast<uint32_t*>(&g_v_hi[o]) = hi2;
                    *reinterpret_cast<uint32_t*>(&g_v_lo[o]) = lo2;
                } else if (MODE == 3) {
                    __nv_bfloat16 h0 = __float2bfloat16(fast_exp(v0 - 64.0f));
                    __nv_bfloat16 h1 = __float2bfloat16(fast_exp(v1 - 64.0f));
                    rsum[fi][h] += __bfloat162float(h0) + __bfloat162float(h1);
                    __nv_bfloat162 hp(h0, h1);
                    size_t o = ((size_t)b*1024 + r)*1024 + c;
                    *reinterpret_cast<uint32_t*>(&g_attn[o]) = *reinterpret_cast<uint32_t*>(&hp);
                } else if (MODE == 4) {
                    float iv = 1.0f / g_S[(size_t)b*1024 + r];
                    uint32_t hi2, lo2; split_pair(v0 * iv, v1 * iv, hi2, lo2);
                    size_t o = ((size_t)b*1024 + r)*256 + c;
                    *reinterpret_cast<uint32_t*>(&g_outT_hi[o]) = hi2;
                    *reinterpret_cast<uint32_t*>(&g_outT_lo[o]) = lo2;
                } else {
                    float sc = p0[r]*rs, bt = p1[r];
                    size_t o = ((size_t)b*512 + r)*1024 + c;
                    float y0 = silu(fmaf(v0, sc, bt)) + p2[o];
                    float y1 = silu(fmaf(v1, sc, bt)) + p2[o + 1];
                    float2 f2 = make_float2(y0, y1);
                    *reinterpret_cast<float2*>(&pout[o]) = f2;
                }
            }
        }
    }

    // MODE 3: deterministic per-CTA row sums -> g_Sp[row][jblock]  (16 jblocks of 64)
    if (MODE == 3) {
        float* bufp = reinterpret_cast<float*>(smem);   // 128 rows x 2 warpN = 1 KB
        __syncthreads();
#pragma unroll
        for (int fi = 0; fi < 2; fi++)
#pragma unroll
            for (int h = 0; h < 2; h++) {
                float v = rsum[fi][h];
                v += __shfl_xor_sync(0xffffffffu, v, 1);
                v += __shfl_xor_sync(0xffffffffu, v, 2);
                if ((lane & 3) == 0) {
                    int rl = warpM + fi*16 + h*8 + (lane >> 2);
                    bufp[rl*2 + (wid >> 2)] = v;
                }
            }
        __syncthreads();
        if (tid < 128) {
            float ssum = bufp[tid*2] + bufp[tid*2 + 1];
            g_Sp[((size_t)b*1024 + m0 + tid)*16 + blockIdx.x] = ssum;
        }
    }
}

// ================= launch =================
extern "C" void kernel_launch(void* const* d_in, const int* in_sizes, int n_in,
                              void* d_out, int out_size) {
    const float* x     = (const float*)d_in[0];
    const float* cv1_w = (const float*)d_in[1];
    const float* cv1_g = (const float*)d_in[2];
    const float* cv1_b = (const float*)d_in[3];
    const float* q_w   = (const float*)d_in[4];
    const float* q_b   = (const float*)d_in[5];
    const float* k_w   = (const float*)d_in[6];
    const float* k_b   = (const float*)d_in[7];
    const float* v_w   = (const float*)d_in[8];
    const float* v_b   = (const float*)d_in[9];
    const float* e_w   = (const float*)d_in[10];
    const float* e_b   = (const float*)d_in[11];
    const float* rel_h = (const float*)d_in[12];
    const float* rel_w = (const float*)d_in[13];
    const float* cv2_w = (const float*)d_in[14];
    const float* cv2_g = (const float*)d_in[15];
    const float* cv2_b = (const float*)d_in[16];
    float* out = (float*)d_out;
    (void)k_b; (void)e_b;

    cudaFuncSetAttribute(gemm_mma<0>, cudaFuncAttributeMaxDynamicSharedMemorySize, SMEM_BYTES);
    cudaFuncSetAttribute(gemm_mma<1>, cudaFuncAttributeMaxDynamicSharedMemorySize, SMEM_BYTES);
    cudaFuncSetAttribute(gemm_mma<2>, cudaFuncAttributeMaxDynamicSharedMemorySize, SMEM_BYTES);
    cudaFuncSetAttribute(gemm_mma<3>, cudaFuncAttributeMaxDynamicSharedMemorySize, SMEM_BYTES);
    cudaFuncSetAttribute(gemm_mma<4>, cudaFuncAttributeMaxDynamicSharedMemorySize, SMEM_BYTES);
    cudaFuncSetAttribute(gemm_mma<5>, cudaFuncAttributeMaxDynamicSharedMemorySize, SMEM_BYTES);

    prep_w<<<1024, 256>>>(cv1_w, v_w, v_b, cv2_w);
    m2_kernel<<<257, 256>>>(q_w, k_w, q_b);
    g_kernel<<<1024, 256>>>(e_w, rel_h, rel_w);
    xt_conv<<<dim3(32, 16, BATCH), dim3(32, 8)>>>(x);

    // cv1: x1T[n][c] = silu(bn(xT @ W1^T))
    gemm_mma<0><<<dim3(4, 8, BATCH), 256, SMEM_BYTES>>>(cv1_g, cv1_b, nullptr, nullptr);
    // uT[n][a] = x1T @ M2^T
    gemm_mma<1><<<dim3(4, 8, BATCH), 256, SMEM_BYTES>>>(nullptr, nullptr, nullptr, nullptr);
    // v[c][n] = Wv @ x1 + bv
    gemm_mma<2><<<dim3(16, 2, BATCH), 256, SMEM_BYTES>>>(nullptr, nullptr, nullptr, nullptr);
    // E[i][j] = exp(x1^T u + G' x1 - 64) (bf16), row partials -> g_Sp
    gemm_mma<3><<<dim3(16, 8, BATCH), 256, SMEM_BYTES>>>(nullptr, nullptr, nullptr, nullptr);
    // S[i] = sum of 16 partials
    sum16_k<<<128, 256>>>();
    // outT[i][c] = (E @ v^T) / S[i]
    gemm_mma<4><<<dim3(4, 8, BATCH), 256, SMEM_BYTES>>>(nullptr, nullptr, nullptr, nullptr);
    // cv2: y[d][n] = x + silu(bn(W2 @ out))
    gemm_mma<5><<<dim3(16, 4, BATCH), 256, SMEM_BYTES>>>(cv2_g, cv2_b, x, out);
}

// round 17
// speedup vs baseline: 1.0257x; 1.0257x over previous
#include <cuda_runtime.h>
#include <cuda_bf16.h>
#include <cstdint>
#include <math.h>

#define BATCH 32

// ================= scratch (device globals) =================
__device__ __align__(256) __nv_bfloat16 g_w1_hi[256*512],  g_w1_lo[256*512];
__device__ __align__(256) __nv_bfloat16 g_wv_hi[256*256],  g_wv_lo[256*256];
__device__ __align__(256) __nv_bfloat16 g_w2_hi[512*256],  g_w2_lo[512*256];
__device__ float g_bv[256];
__device__ float g_r[256];
__device__ __align__(256) __nv_bfloat16 g_M2_hi[256*256],  g_M2_lo[256*256];
__device__ __align__(256) __nv_bfloat16 g_G_hi[1024*256],  g_G_lo[1024*256];
__device__ float g_S[(size_t)BATCH*1024];
__device__ float g_Sp[(size_t)BATCH*1024*16];
__device__ __align__(256) __nv_bfloat16 g_xT_hi[(size_t)BATCH*1024*512], g_xT_lo[(size_t)BATCH*1024*512];
__device__ __align__(256) __nv_bfloat16 g_x1T_hi[(size_t)BATCH*1024*256], g_x1T_lo[(size_t)BATCH*1024*256];
__device__ __align__(256) __nv_bfloat16 g_uT_hi[(size_t)BATCH*1024*256], g_uT_lo[(size_t)BATCH*1024*256];
__device__ __align__(256) __nv_bfloat16 g_v_hi[(size_t)BATCH*256*1024],  g_v_lo[(size_t)BATCH*256*1024];
__device__ __align__(256) __nv_bfloat16 g_attn[(size_t)BATCH*1024*1024];
__device__ __align__(256) __nv_bfloat16 g_outT_hi[(size_t)BATCH*1024*256], g_outT_lo[(size_t)BATCH*1024*256];

// ================= helpers =================
__device__ __forceinline__ uint32_t smem_u32(const void* p) {
    uint32_t a;
    asm("{ .reg .u64 t; cvta.to.shared.u64 t, %1; cvt.u32.u64 %0, t; }" : "=r"(a) : "l"(p));
    return a;
}
__device__ __forceinline__ void cp16(uint32_t s, const void* g) {
    asm volatile("cp.async.cg.shared.global [%0], [%1], 16;" :: "r"(s), "l"(g) : "memory");
}
#define CP_COMMIT() asm volatile("cp.async.commit_group;" ::: "memory")
#define CP_WAIT0()  asm volatile("cp.async.wait_group 0;" ::: "memory")
#define CP_WAIT1()  asm volatile("cp.async.wait_group 1;" ::: "memory")

__device__ __forceinline__ void ldsm4(uint32_t* r, uint32_t addr) {
    asm volatile("ldmatrix.sync.aligned.m8n8.x4.shared.b16 {%0,%1,%2,%3}, [%4];"
        : "=r"(r[0]), "=r"(r[1]), "=r"(r[2]), "=r"(r[3]) : "r"(addr));
}
__device__ __forceinline__ void mma16816(float* c, const uint32_t* a, const uint32_t* b) {
    asm volatile("mma.sync.aligned.m16n8k16.row.col.f32.bf16.bf16.f32 "
        "{%0,%1,%2,%3}, {%4,%5,%6,%7}, {%8,%9}, {%0,%1,%2,%3};"
        : "+f"(c[0]), "+f"(c[1]), "+f"(c[2]), "+f"(c[3])
        : "r"(a[0]), "r"(a[1]), "r"(a[2]), "r"(a[3]), "r"(b[0]), "r"(b[1]));
}
__device__ __forceinline__ void bsplit(float v, __nv_bfloat16& h, __nv_bfloat16& l) {
    h = __float2bfloat16(v);
    l = __float2bfloat16(v - __bfloat162float(h));
}
__device__ __forceinline__ void split_pair(float v0, float v1, uint32_t& hi2, uint32_t& lo2) {
    __nv_bfloat16 h0, l0, h1, l1;
    bsplit(v0, h0, l0); bsplit(v1, h1, l1);
    __nv_bfloat162 h = __nv_bfloat162(h0, h1), l = __nv_bfloat162(l0, l1);
    hi2 = *reinterpret_cast<uint32_t*>(&h);
    lo2 = *reinterpret_cast<uint32_t*>(&l);
}
__device__ __forceinline__ float silu(float t) { return t / (1.0f + __expf(-t)); }

// ================= prep kernels =================
// blocks 0..256: M2/r;  blocks 257..768: weight hi/lo splits
__global__ void prep_m2_kernel(const float* __restrict__ qw, const float* __restrict__ kw,
                               const float* __restrict__ qb,
                               const float* __restrict__ w1, const float* __restrict__ vw,
                               const float* __restrict__ vb, const float* __restrict__ w2) {
    int blk = blockIdx.x;
    if (blk <= 256) {
        int a = blk, bcol = threadIdx.x;
        float acc = 0.f;
        if (a < 256) {
            for (int o = 0; o < 256; o++) acc += qw[o*256 + a] * kw[o*256 + bcol];
            bsplit(acc, g_M2_hi[a*256 + bcol], g_M2_lo[a*256 + bcol]);
        } else {
            for (int o = 0; o < 256; o++) acc += qb[o] * kw[o*256 + bcol];
            g_r[bcol] = acc;
        }
    } else {
        int t = (blk - 257) * 256 + threadIdx.x;   // 0 .. 131071
        if (t < 256*512) bsplit(w1[t], g_w1_hi[t], g_w1_lo[t]);
        if (t < 256*256) bsplit(vw[t], g_wv_hi[t], g_wv_lo[t]);
        if (t < 512*256) bsplit(w2[t], g_w2_hi[t], g_w2_lo[t]);
        if (t < 256) g_bv[t] = vb[t];
    }
}

// G'[i][b] = sum_a pos[a][i]*We[a][b] + r[b]   (prep_m2 runs first)
__global__ void g_kernel(const float* __restrict__ ew, const float* __restrict__ rh,
                         const float* __restrict__ rw) {
    int i = blockIdx.x, bcol = threadIdx.x;
    int h = i >> 5, w = i & 31;
    float acc = g_r[bcol];
    for (int a = 0; a < 256; a++) {
        float pv = rh[a*32 + h] + rw[a*32 + w];
        acc += pv * ew[a*256 + bcol];
    }
    bsplit(acc, g_G_hi[i*256 + bcol], g_G_lo[i*256 + bcol]);
}

// S[row] = sum of 16 per-jblock partials
__global__ void sum16_k() {
    int t = blockIdx.x * blockDim.x + threadIdx.x;   // 32768
    const float* p = g_Sp + (size_t)t * 16;
    float s = 0.f;
#pragma unroll
    for (int c = 0; c < 16; c++) s += p[c];
    g_S[t] = s;
}

// transpose + split x: [b][d][n] fp32 -> xT[b][n][d] bf16 hi/lo
__global__ void xt_conv(const float* __restrict__ x) {
    __shared__ float tile[32][33];
    int b = blockIdx.z, d0 = blockIdx.y*32, n0 = blockIdx.x*32;
    int tx = threadIdx.x, ty = threadIdx.y;  // 32 x 8
    const float* xp = x + ((size_t)b*512 + d0)*1024 + n0;
#pragma unroll
    for (int r = 0; r < 4; r++) tile[ty + r*8][tx] = xp[(size_t)(ty + r*8)*1024 + tx];
    __syncthreads();
#pragma unroll
    for (int r = 0; r < 4; r++) {
        int nl = ty + r*8;
        __nv_bfloat16 h, l; bsplit(tile[tx][nl], h, l);
        size_t o = ((size_t)b*1024 + n0 + nl)*512 + d0 + tx;
        g_xT_hi[o] = h; g_xT_lo[o] = l;
    }
}

// ===== fused-3-product warp-MMA GEMM, occupancy-3 geometry (R15-proven) =====
// CTA 128x64, BK=32, 8 warps (4x2) of 32x32, 3-stage pipeline, 3 CTAs/SM.
// MODE 0: cv1    M=n(1024) N=c(256)  K=512  -> x1T
// MODE 12: fused u (t<32) and v (t>=32)     -> uT / v
// MODE 3: logits M=i(1024) N=j(1024) K=512  -> E bf16 + row partials (16 jblocks)
// MODE 4: out    M=i(1024) N=c(256)  K=1024 -> outT
// MODE 5: cv2    M=d(512)  N=n(1024) K=256  -> d_out
#define A_TILE 8192
#define B_TILE 4096
#define STAGE_BYTES 24576
#define SMEM_BYTES  73728

template <int MODE>
__global__ void __launch_bounds__(256, 3)
gemm_mma(const float* __restrict__ p0, const float* __restrict__ p1,
         const float* __restrict__ p2, float* __restrict__ pout) {
    constexpr int K   = (MODE==0 || MODE==3) ? 512 : (MODE==4 ? 1024 : 256);
    constexpr int KIT = K / 32;
    constexpr int ST  = (MODE==0) ? 512 : (MODE==4 ? 1024 : 256);
    constexpr bool ALO = (MODE != 4);

    extern __shared__ char smem[];
    const uint32_t sbase = smem_u32(smem);
    const int tid = threadIdx.x, wid = tid >> 5, lane = tid & 31;
    const int b = blockIdx.z;
    // MODE12: flat blockIdx.x dispatch between u-GEMM and v-GEMM
    int m0_, n0_; bool isU_ = true;
    if (MODE == 12) {
        int t = blockIdx.x;
        if (t < 32) { m0_ = (t >> 2) * 128; n0_ = (t & 3) * 64; isU_ = true; }
        else { int t2 = t - 32; m0_ = (t2 >> 4) * 128; n0_ = (t2 & 15) * 64; isU_ = false; }
    } else {
        m0_ = blockIdx.y * 128; n0_ = blockIdx.x * 64;
    }
    const int m0 = m0_, n0 = n0_; const bool isU = isU_;
    const int warpM = (wid & 3) * 32, warpN = (wid >> 2) * 32;
    const int rsel = lane & 15, csel = lane >> 4;

    uint32_t aSw[2]; int aRow[2], aQ[2];
#pragma unroll
    for (int c = 0; c < 2; c++) {
        int idx = tid + c*256;
        aRow[c] = idx >> 2; aQ[c] = idx & 3;
        aSw[c] = (uint32_t)(aRow[c]*64 + ((aQ[c] ^ ((aRow[c] >> 1) & 3)) << 4));
    }
    const int bRow = tid >> 2, bQ = tid & 3;
    const uint32_t bSw = (uint32_t)(bRow*64 + ((bQ ^ ((bRow >> 1) & 3)) << 4));

    uint32_t offA[2][2], offB[2][2];
#pragma unroll
    for (int fi = 0; fi < 2; fi++) {
        int row = warpM + fi*16 + rsel;
        int rsw = (row >> 1) & 3;
#pragma unroll
        for (int ks = 0; ks < 2; ks++)
            offA[fi][ks] = (uint32_t)(row*64 + (((ks*2 + csel) ^ rsw) << 4));
    }
#pragma unroll
    for (int fj = 0; fj < 2; fj++) {
        int row = warpN + fj*16 + rsel;
        int rsw = (row >> 1) & 3;
#pragma unroll
        for (int ks = 0; ks < 2; ks++)
            offB[fj][ks] = (uint32_t)(row*64 + (((ks*2 + csel) ^ rsw) << 4));
    }

    const __nv_bfloat16 *pAh, *pAl, *pBh, *pBl;
    auto get_ptrs = [&](int kc) {
        if (MODE == 0) {
            size_t ao = ((size_t)b*1024 + m0)*512 + kc*32;
            pAh = g_xT_hi + ao; pAl = g_xT_lo + ao;
            size_t bo = (size_t)n0*512 + kc*32;
            pBh = g_w1_hi + bo; pBl = g_w1_lo + bo;
        } else if (MODE == 12) {
            if (isU) {
                size_t ao = ((size_t)b*1024 + m0)*256 + kc*32;
                pAh = g_x1T_hi + ao; pAl = g_x1T_lo + ao;
                size_t bo = (size_t)n0*256 + kc*32;
                pBh = g_M2_hi + bo; pBl = g_M2_lo + bo;
            } else {
                size_t ao = (size_t)m0*256 + kc*32;
                pAh = g_wv_hi + ao; pAl = g_wv_lo + ao;
                size_t bo = ((size_t)b*1024 + n0)*256 + kc*32;
                pBh = g_x1T_hi + bo; pBl = g_x1T_lo + bo;
            }
        } else if (MODE == 3) {
            if (kc < 8) {
                size_t ao = ((size_t)b*1024 + m0)*256 + kc*32;
                pAh = g_x1T_hi + ao; pAl = g_x1T_lo + ao;
                size_t bo = ((size_t)b*1024 + n0)*256 + kc*32;
                pBh = g_uT_hi + bo; pBl = g_uT_lo + bo;
            } else {
                size_t ao = (size_t)m0*256 + (kc - 8)*32;
                pAh = g_G_hi + ao; pAl = g_G_lo + ao;
                size_t bo = ((size_t)b*1024 + n0)*256 + (kc - 8)*32;
                pBh = g_x1T_hi + bo; pBl = g_x1T_lo + bo;
            }
        } else if (MODE == 4) {
            size_t ao = ((size_t)b*1024 + m0)*1024 + kc*32;
            pAh = g_attn + ao; pAl = pAh;
            size_t bo = ((size_t)b*256 + n0)*1024 + kc*32;
            pBh = g_v_hi + bo; pBl = g_v_lo + bo;
        } else {
            size_t ao = (size_t)m0*256 + kc*32;
            pAh = g_w2_hi + ao; pAl = g_w2_lo + ao;
            size_t bo = ((size_t)b*1024 + n0)*256 + kc*32;
            pBh = g_outT_hi + bo; pBl = g_outT_lo + bo;
        }
    };
    auto issue = [&](int buf) {
        uint32_t s0 = sbase + (uint32_t)buf*STAGE_BYTES;
#pragma unroll
        for (int c = 0; c < 2; c++) {
            size_t go = (size_t)aRow[c]*ST + aQ[c]*8;
            cp16(s0 + aSw[c], pAh + go);
            if (ALO) cp16(s0 + A_TILE + aSw[c], pAl + go);
        }
        size_t gb = (size_t)bRow*ST + bQ*8;
        cp16(s0 + 2*A_TILE + bSw, pBh + gb);
        cp16(s0 + 2*A_TILE + B_TILE + bSw, pBl + gb);
        CP_COMMIT();
    };

    float acc[2][4][4] = {};

    get_ptrs(0); issue(0);
    get_ptrs(1); issue(1);
    CP_WAIT1();
    __syncthreads();

    int buf = 0;
    for (int it = 0; it < KIT; ++it) {
        if (it + 2 < KIT) {
            get_ptrs(it + 2);
            issue((buf + 2) % 3);
        }
        const uint32_t aH = sbase + (uint32_t)buf*STAGE_BYTES;
        const uint32_t aL = aH + A_TILE;
        const uint32_t bH = aH + 2*A_TILE;
        const uint32_t bL = bH + B_TILE;
#pragma unroll
        for (int ks = 0; ks < 2; ++ks) {
            uint32_t ah[2][4], bh[2][4], bl[2][4];
#pragma unroll
            for (int fi = 0; fi < 2; fi++) ldsm4(ah[fi], aH + offA[fi][ks]);
#pragma unroll
            for (int fj = 0; fj < 2; fj++) ldsm4(bh[fj], bH + offB[fj][ks]);
#pragma unroll
            for (int fj = 0; fj < 2; fj++) ldsm4(bl[fj], bL + offB[fj][ks]);
#pragma unroll
            for (int fi = 0; fi < 2; fi++)
#pragma unroll
                for (int fj = 0; fj < 4; fj++) {
                    uint32_t bb[2] = { bh[fj >> 1][fj & 1], bh[fj >> 1][2 + (fj & 1)] };
                    mma16816(acc[fi][fj], ah[fi], bb);
                }
#pragma unroll
            for (int fi = 0; fi < 2; fi++)
#pragma unroll
                for (int fj = 0; fj < 4; fj++) {
                    uint32_t bb[2] = { bl[fj >> 1][fj & 1], bl[fj >> 1][2 + (fj & 1)] };
                    mma16816(acc[fi][fj], ah[fi], bb);
                }
            if (ALO) {
                uint32_t al[2][4];
#pragma unroll
                for (int fi = 0; fi < 2; fi++) ldsm4(al[fi], aL + offA[fi][ks]);
#pragma unroll
                for (int fi = 0; fi < 2; fi++)
#pragma unroll
                    for (int fj = 0; fj < 4; fj++) {
                        uint32_t bb[2] = { bh[fj >> 1][fj & 1], bh[fj >> 1][2 + (fj & 1)] };
                        mma16816(acc[fi][fj], al[fi], bb);
                    }
            }
        }
        if (it + 1 < KIT) {
            if (it + 2 < KIT) CP_WAIT1(); else CP_WAIT0();
            __syncthreads();
        }
        buf = (buf + 1) % 3;
    }

    // ---- epilogue ----
    const float rs = rsqrtf(1.0f + 1e-5f);
    float rsum[2][2] = {};
#pragma unroll
    for (int fi = 0; fi < 2; fi++) {
        int r0 = m0 + warpM + fi*16 + (lane >> 2);
#pragma unroll
        for (int fj = 0; fj < 4; fj++) {
            int c = n0 + warpN + fj*8 + (lane & 3)*2;
#pragma unroll
            for (int h = 0; h < 2; h++) {
                int r = r0 + h*8;
                float v0 = acc[fi][fj][h*2], v1 = acc[fi][fj][h*2 + 1];
                if (MODE == 0) {
                    float t0 = fmaf(v0, p0[c]*rs,   p1[c]);
                    float t1 = fmaf(v1, p0[c+1]*rs, p1[c+1]);
                    uint32_t hi2, lo2; split_pair(silu(t0), silu(t1), hi2, lo2);
                    size_t o = ((size_t)b*1024 + r)*256 + c;
                    *reinterpret_cast<uint32_t*>(&g_x1T_hi[o]) = hi2;
                    *reinterpret_cast<uint32_t*>(&g_x1T_lo[o]) = lo2;
                } else if (MODE == 12) {
                    if (isU) {
                        uint32_t hi2, lo2; split_pair(v0, v1, hi2, lo2);
                        size_t o = ((size_t)b*1024 + r)*256 + c;
                        *reinterpret_cast<uint32_t*>(&g_uT_hi[o]) = hi2;
                        *reinterpret_cast<uint32_t*>(&g_uT_lo[o]) = lo2;
                    } else {
                        float bi = g_bv[r];
                        uint32_t hi2, lo2; split_pair(v0 + bi, v1 + bi, hi2, lo2);
                        size_t o = ((size_t)b*256 + r)*1024 + c;
                        *reinterpret_cast<uint32_t*>(&g_v_hi[o]) = hi2;
                        *reinterpret_cast<uint32_t*>(&g_v_lo[o]) = lo2;
                    }
                } else if (MODE == 3) {
                    __nv_bfloat16 h0 = __float2bfloat16(__expf(v0 - 64.0f));
                    __nv_bfloat16 h1 = __float2bfloat16(__expf(v1 - 64.0f));
                    rsum[fi][h] += __bfloat162float(h0) + __bfloat162float(h1);
                    __nv_bfloat162 hp(h0, h1);
                    size_t o = ((size_t)b*1024 + r)*1024 + c;
                    *reinterpret_cast<uint32_t*>(&g_attn[o]) = *reinterpret_cast<uint32_t*>(&hp);
                } else if (MODE == 4) {
                    float iv = 1.0f / g_S[(size_t)b*1024 + r];
                    uint32_t hi2, lo2; split_pair(v0 * iv, v1 * iv, hi2, lo2);
                    size_t o = ((size_t)b*1024 + r)*256 + c;
                    *reinterpret_cast<uint32_t*>(&g_outT_hi[o]) = hi2;
                    *reinterpret_cast<uint32_t*>(&g_outT_lo[o]) = lo2;
                } else {
                    float sc = p0[r]*rs, bt = p1[r];
                    size_t o = ((size_t)b*512 + r)*1024 + c;
                    float y0 = silu(fmaf(v0, sc, bt)) + p2[o];
                    float y1 = silu(fmaf(v1, sc, bt)) + p2[o + 1];
                    float2 f2 = make_float2(y0, y1);
                    *reinterpret_cast<float2*>(&pout[o]) = f2;
                }
            }
        }
    }

    // MODE 3: deterministic per-CTA row sums -> g_Sp[row][jblock]  (16 jblocks of 64)
    if (MODE == 3) {
        float* bufp = reinterpret_cast<float*>(smem);   // 128 rows x 2 warpN = 1 KB
        __syncthreads();
#pragma unroll
        for (int fi = 0; fi < 2; fi++)
#pragma unroll
            for (int h = 0; h < 2; h++) {
                float v = rsum[fi][h];
                v += __shfl_xor_sync(0xffffffffu, v, 1);
                v += __shfl_xor_sync(0xffffffffu, v, 2);
                if ((lane & 3) == 0) {
                    int rl = warpM + fi*16 + h*8 + (lane >> 2);
                    bufp[rl*2 + (wid >> 2)] = v;
                }
            }
        __syncthreads();
        if (tid < 128) {
            float ssum = bufp[tid*2] + bufp[tid*2 + 1];
            g_Sp[((size_t)b*1024 + m0 + tid)*16 + blockIdx.x] = ssum;
        }
    }
}

// ================= launch =================
extern "C" void kernel_launch(void* const* d_in, const int* in_sizes, int n_in,
                              void* d_out, int out_size) {
    const float* x     = (const float*)d_in[0];
    const float* cv1_w = (const float*)d_in[1];
    const float* cv1_g = (const float*)d_in[2];
    const float* cv1_b = (const float*)d_in[3];
    const float* q_w   = (const float*)d_in[4];
    const float* q_b   = (const float*)d_in[5];
    const float* k_w   = (const float*)d_in[6];
    const float* k_b   = (const float*)d_in[7];
    const float* v_w   = (const float*)d_in[8];
    const float* v_b   = (const float*)d_in[9];
    const float* e_w   = (const float*)d_in[10];
    const float* e_b   = (const float*)d_in[11];
    const float* rel_h = (const float*)d_in[12];
    const float* rel_w = (const float*)d_in[13];
    const float* cv2_w = (const float*)d_in[14];
    const float* cv2_g = (const float*)d_in[15];
    const float* cv2_b = (const float*)d_in[16];
    float* out = (float*)d_out;
    (void)k_b; (void)e_b;

    cudaFuncSetAttribute(gemm_mma<0>,  cudaFuncAttributeMaxDynamicSharedMemorySize, SMEM_BYTES);
    cudaFuncSetAttribute(gemm_mma<12>, cudaFuncAttributeMaxDynamicSharedMemorySize, SMEM_BYTES);
    cudaFuncSetAttribute(gemm_mma<3>,  cudaFuncAttributeMaxDynamicSharedMemorySize, SMEM_BYTES);
    cudaFuncSetAttribute(gemm_mma<4>,  cudaFuncAttributeMaxDynamicSharedMemorySize, SMEM_BYTES);
    cudaFuncSetAttribute(gemm_mma<5>,  cudaFuncAttributeMaxDynamicSharedMemorySize, SMEM_BYTES);

    prep_m2_kernel<<<769, 256>>>(q_w, k_w, q_b, cv1_w, v_w, v_b, cv2_w);
    g_kernel<<<1024, 256>>>(e_w, rel_h, rel_w);
    xt_conv<<<dim3(32, 16, BATCH), dim3(32, 8)>>>(x);

    // cv1: x1T[n][c] = silu(bn(xT @ W1^T))
    gemm_mma<0><<<dim3(4, 8, BATCH), 256, SMEM_BYTES>>>(cv1_g, cv1_b, nullptr, nullptr);
    // fused u (uT = x1T @ M2^T) + v (v = Wv @ x1 + bv)
    gemm_mma<12><<<dim3(64, 1, BATCH), 256, SMEM_BYTES>>>(nullptr, nullptr, nullptr, nullptr);
    // E[i][j] = exp(x1^T u + G' x1 - 64) (bf16), row partials -> g_Sp
    gemm_mma<3><<<dim3(16, 8, BATCH), 256, SMEM_BYTES>>>(nullptr, nullptr, nullptr, nullptr);
    // S[i] = sum of 16 partials
    sum16_k<<<128, 256>>>();
    // outT[i][c] = (E @ v^T) / S[i]
    gemm_mma<4><<<dim3(4, 8, BATCH), 256, SMEM_BYTES>>>(nullptr, nullptr, nullptr, nullptr);
    // cv2: y[d][n] = x + silu(bn(W2 @ out))
    gemm_mma<5><<<dim3(16, 4, BATCH), 256, SMEM_BYTES>>>(cv2_g, cv2_b, x, out);
}